// round 10
// baseline (speedup 1.0000x reference)
#include <cuda_runtime.h>

// ---------------------------------------------------------------------------
// MaskRemoval — R10: scan fast paths (class-size specialization).
//   k_bits  : grid (N,24). y<16 zero-writers (first), y>=16 raster slices.
//   k_scan  : grid (NCLS). k=0 -> exit; k=1 -> keep=msum>0 (no mask work);
//             k>=2 -> union-rect mask zero, skip overlap until mask nonempty,
//             skip merge on last ROI.
//   k_paste : grid (N+1,8). warp-per-row bilinear paste; CTA N -> keep_inds.
// ---------------------------------------------------------------------------

#define MAXN   128
#define NCLS   80
#define MM     28
#define IMG_H  800
#define IMG_W  800
#define WPR    25                      // 800/32 words per image row
#define BOXMAX 384
#define NSPLIT 8                       // raster y-slices per ROI
#define ZSPLIT 16                      // zero-writer CTA columns (first!)
#define BITSW  8192                    // words of bit-scratch per ROI
#define CMASK_BYTES (IMG_H * WPR * 4)  // 80000 B dynamic smem for k_scan

__device__ int g_keep[MAXN];
__device__ int g_msumP[MAXN][NSPLIT];            // per-slice popcounts
__device__ unsigned int g_bits[MAXN][BITSW];     // 4 MB ROI bit rasters

// exact reference bilinear form (keep decision thresholds on val>0)
__device__ __forceinline__ float bilin_ref(const float* lg, float sx, float sy) {
    int ix0 = (int)sx;
    int iy0 = (int)sy;
    int ix1 = min(ix0 + 1, MM - 1);
    int iy1 = min(iy0 + 1, MM - 1);
    float fx = sx - (float)ix0;
    float fy = sy - (float)iy0;
    float v00 = lg[iy0 * MM + ix0], v01 = lg[iy0 * MM + ix1];
    float v10 = lg[iy1 * MM + ix0], v11 = lg[iy1 * MM + ix1];
    return (1.0f - fy) * ((1.0f - fx) * v00 + fx * v01)
         +         fy  * ((1.0f - fx) * v10 + fx * v11);
}

// stable descending rank sort into smem: sord[rank] = original index
__device__ __forceinline__ void stage_sort(const float* __restrict__ prob,
                                           int N, float* sp, int* sord) {
    int t = threadIdx.x;
    if (t < N) sp[t] = prob[t];
    __syncthreads();
    if (t < N) {
        float pi = sp[t];
        int r = 0;
        for (int j = 0; j < N; j++) {
            float pj = sp[j];
            r += (pj > pi) || (pj == pi && j < t);
        }
        sord[r] = t;
    }
    __syncthreads();
}

// ---------------------------------------------------------------------------
// grid (N, ZSPLIT+NSPLIT): y<ZSPLIT zero-writer (dispatched first),
// y in [ZSPLIT, ZSPLIT+NSPLIT) raster slice.
__global__ __launch_bounds__(256) void k_bits(const float* __restrict__ rois,
                                              const float* __restrict__ prob,
                                              const float* __restrict__ mask_prob,
                                              float4* __restrict__ energy4,
                                              long long n4, int N) {
    if (blockIdx.y < ZSPLIT) {
        long long wid = (long long)blockIdx.x + (long long)N * blockIdx.y;
        long long nthreads = (long long)N * ZSPLIT * blockDim.x;
        long long i = wid * blockDim.x + threadIdx.x;
        float4 z = make_float4(0.f, 0.f, 0.f, 0.f);
        long long s4 = 4 * nthreads;
        for (; i + 3 * nthreads < n4; i += s4) {
            __stcs(&energy4[i], z);
            __stcs(&energy4[i + nthreads], z);
            __stcs(&energy4[i + 2 * nthreads], z);
            __stcs(&energy4[i + 3 * nthreads], z);
        }
        for (; i < n4; i += nthreads) __stcs(&energy4[i], z);
        return;
    }
    int slice = blockIdx.y - ZSPLIT;

    __shared__ float sp[MAXN];
    __shared__ int   sord[MAXN];
    __shared__ float lg[MM * MM];
    __shared__ float2 s_cx[BOXMAX];
    __shared__ int   s_cnt;

    int i = blockIdx.x;
    if (i >= N) return;
    stage_sort(prob, N, sp, sord);

    int o = sord[i];
    float4 rb = reinterpret_cast<const float4*>(rois)[o];
    int x0 = (int)rb.x, y0 = (int)rb.y, x1 = (int)rb.z, y1 = (int)rb.w;
    int xs0 = max(x0, 0), xs1 = min(x1 + 1, IMG_W);
    int ys0 = max(y0, 0), ys1 = min(y1 + 1, IMG_H);
    int bw = xs1 - xs0, bh = ys1 - ys0;
    if (bw <= 0 || bh <= 0) return;        // g_msumP slot never written => 0

    if (threadIdx.x == 0) s_cnt = 0;
    const float* lp = mask_prob + (long long)o * (MM * MM);
    for (int t = threadIdx.x; t < MM * MM; t += blockDim.x) lg[t] = lp[t];

    float wv = fmaxf((float)(x1 - x0 + 1), 1.0f);
    float hv = fmaxf((float)(y1 - y0 + 1), 1.0f);
    float scx = 28.0f / wv, scy = 28.0f / hv;

    bool pre = (bw <= BOXMAX);
    if (pre) {
        for (int t = threadIdx.x; t < bw; t += blockDim.x) {
            float sx = fminf(fmaxf(((float)(xs0 + t) - (float)x0 + 0.5f) * scx - 0.5f, 0.0f), 27.0f);
            int ix0 = (int)sx;
            s_cx[t] = make_float2(sx - (float)ix0, __int_as_float(ix0));
        }
    }
    __syncthreads();

    int chunk = (bh + NSPLIT - 1) / NSPLIT;
    int ry0   = slice * chunk;
    int rows  = min(chunk, bh - ry0);
    if (rows <= 0) return;

    int xw0 = xs0 >> 5, xw1 = (xs1 + 31) >> 5;
    int nwx = xw1 - xw0;
    bool fits = (nwx * bh <= BITSW);

    int warp = threadIdx.x >> 5;
    int lane = threadIdx.x & 31;
    int nwarps = blockDim.x >> 5;
    int lm = 0;

    for (int r = warp; r < rows; r += nwarps) {
        int ry = ry0 + r;
        int y  = ys0 + ry;
        float sy = fminf(fmaxf(((float)y - (float)y0 + 0.5f) * scy - 0.5f, 0.0f), 27.0f);
        int iy0 = (int)sy;
        int iy1 = min(iy0 + 1, MM - 1);
        float fy = sy - (float)iy0;
        int ll = min(lane, MM - 1);
        float r0v = lg[iy0 * MM + ll];
        float r1v = lg[iy1 * MM + ll];

        unsigned int* dst = fits ? &g_bits[i][ry * nwx] : nullptr;
        for (int xw = xw0; xw < xw1; xw++) {
            int x = (xw << 5) + lane;
            bool inb = (x >= xs0) && (x < xs1);
            float val;
            if (pre) {
                float2 cf = s_cx[inb ? (x - xs0) : 0];
                float fx = cf.x;
                int ix0 = __float_as_int(cf.y);
                int ix1 = min(ix0 + 1, MM - 1);
                float v00 = __shfl_sync(0xffffffffu, r0v, ix0);
                float v01 = __shfl_sync(0xffffffffu, r0v, ix1);
                float v10 = __shfl_sync(0xffffffffu, r1v, ix0);
                float v11 = __shfl_sync(0xffffffffu, r1v, ix1);
                val = (1.0f - fy) * ((1.0f - fx) * v00 + fx * v01)
                    +         fy  * ((1.0f - fx) * v10 + fx * v11);
            } else {
                float sx = fminf(fmaxf(((float)x - (float)x0 + 0.5f) * scx - 0.5f, 0.0f), 27.0f);
                val = bilin_ref(lg, sx, sy);
            }
            bool on = inb && (val > 0.0f);
            unsigned int bits = __ballot_sync(0xffffffffu, on);
            if (lane == 0) {
                if (dst) dst[xw - xw0] = bits;
                lm += __popc(bits);
            }
        }
    }
    if (lane == 0 && lm) atomicAdd(&s_cnt, lm);
    __syncthreads();
    if (threadIdx.x == 0) g_msumP[i][slice] = s_cnt;
}

// ---------------------------------------------------------------------------
// Per-class suppression with class-size fast paths.
__global__ __launch_bounds__(256) void k_scan(const float* __restrict__ rois,
                                              const float* __restrict__ prob,
                                              const int*   __restrict__ clsidx,
                                              const float* __restrict__ mask_prob,
                                              int N) {
    extern __shared__ unsigned int sm_mask[];               // IMG_H*WPR words
    __shared__ float sp[MAXN];
    __shared__ int   sord[MAXN];
    __shared__ int   scls[MAXN];
    __shared__ int   s_list[MAXN];
    __shared__ int   s_k;
    __shared__ int   s_gx0[16], s_gx1[16], s_gy0[16], s_gy1[16]; // clipped geom
    __shared__ int   s_ext[4];                               // union rect
    __shared__ int   s_ovl, s_keep;
    __shared__ float lg[MM * MM];

    int c = blockIdx.x;
    int t = threadIdx.x;

    // self-staging sort + class per sorted slot
    if (t < N) sp[t] = prob[t];
    __syncthreads();
    if (t < N) {
        float pi = sp[t];
        int r = 0;
        for (int j = 0; j < N; j++) {
            float pj = sp[j];
            r += (pj > pi) || (pj == pi && j < t);
        }
        sord[r] = t;
        scls[r] = clsidx[t] - 1;
    }
    __syncthreads();

    // class ROI list (sorted order preserved)
    if (t == 0) {
        int k = 0;
        for (int i = 0; i < N; i++)
            if (scls[i] == c) s_list[k++] = i;
        s_k = k;
    }
    __syncthreads();
    int k = s_k;
    if (k == 0) return;

    // ---- k == 1: no suppression possible -----------------------------------
    if (k == 1) {
        if (t == 0) {
            int i = s_list[0];
            int msum = 0;
            #pragma unroll
            for (int u = 0; u < NSPLIT; u++) msum += g_msumP[i][u];
            g_keep[i] = (msum > 0);
        }
        return;
    }

    // ---- k >= 2: stage clipped geometry, compute union rect ---------------
    int kc = min(k, 16);
    if (t < kc) {
        int i = s_list[t];
        float4 rb = reinterpret_cast<const float4*>(rois)[sord[i]];
        int x0 = (int)rb.x, y0 = (int)rb.y, x1 = (int)rb.z, y1 = (int)rb.w;
        s_gx0[t] = max(x0, 0);
        s_gx1[t] = min(x1 + 1, IMG_W);
        s_gy0[t] = max(y0, 0);
        s_gy1[t] = min(y1 + 1, IMG_H);
    }
    __syncthreads();
    if (t == 0) {
        int ux0 = IMG_W, ux1 = 0, uy0 = IMG_H, uy1 = 0;
        for (int j = 0; j < kc; j++) {
            if (s_gx0[j] < s_gx1[j] && s_gy0[j] < s_gy1[j]) {
                ux0 = min(ux0, s_gx0[j]); ux1 = max(ux1, s_gx1[j]);
                uy0 = min(uy0, s_gy0[j]); uy1 = max(uy1, s_gy1[j]);
            }
        }
        s_ext[0] = ux0 >> 5;                 // union word col start
        s_ext[1] = (ux1 + 31) >> 5;          // union word col end
        s_ext[2] = uy0;                      // union row start
        s_ext[3] = uy1;                      // union row end
    }
    __syncthreads();
    int uw0 = s_ext[0], uw1 = s_ext[1], uy0 = s_ext[2], uy1 = s_ext[3];
    int unw = max(uw1 - uw0, 0);
    int unrows = max(uy1 - uy0, 0);

    // zero only the union rectangle of the class mask
    for (int w = t; w < unw * unrows; w += blockDim.x) {
        int r = w / unw;
        sm_mask[(uy0 + r) * WPR + uw0 + (w - r * unw)] = 0u;
    }
    __syncthreads();

    bool mask_ne = false;                    // class mask nonempty?

    for (int j = 0; j < k; j++) {
        int i = s_list[j];
        int msum = 0;
        #pragma unroll
        for (int u = 0; u < NSPLIT; u++) msum += g_msumP[i][u];
        if (msum == 0) { if (t == 0) g_keep[i] = 0; continue; }

        int xs0, xs1, ys0, ys1;
        if (j < 16) {
            xs0 = s_gx0[j]; xs1 = s_gx1[j]; ys0 = s_gy0[j]; ys1 = s_gy1[j];
        } else {
            float4 rb = reinterpret_cast<const float4*>(rois)[sord[i]];
            xs0 = max((int)rb.x, 0); xs1 = min((int)rb.z + 1, IMG_W);
            ys0 = max((int)rb.y, 0); ys1 = min((int)rb.w + 1, IMG_H);
        }
        int bh = ys1 - ys0;
        int xw0 = xs0 >> 5, xw1 = (xs1 + 31) >> 5;
        int nwx = xw1 - xw0;
        int total = nwx * bh;
        bool fits = (total <= BITSW);

        if (t == 0) s_ovl = 0;
        __syncthreads();

        // overlap pass only when the class mask has content
        if (mask_ne) {
            int lo = 0;
            if (fits) {
                const unsigned int* bi = g_bits[i];
                for (int kk = t; kk < total; kk += blockDim.x) {
                    unsigned int b = bi[kk];
                    if (b) {
                        int ry = kk / nwx;
                        int xw = xw0 + (kk - ry * nwx);
                        lo += __popc(b & sm_mask[(ys0 + ry) * WPR + xw]);
                    }
                }
            } else {
                int o = sord[i];
                const float* lp = mask_prob + (long long)o * (MM * MM);
                for (int u = t; u < MM * MM; u += blockDim.x) lg[u] = lp[u];
                __syncthreads();
                float4 rb = reinterpret_cast<const float4*>(rois)[o];
                int x0 = (int)rb.x, y0 = (int)rb.y, x1 = (int)rb.z, y1 = (int)rb.w;
                float wv = fmaxf((float)(x1 - x0 + 1), 1.0f);
                float hv = fmaxf((float)(y1 - y0 + 1), 1.0f);
                float scx = 28.0f / wv, scy = 28.0f / hv;
                for (int kk = t; kk < total; kk += blockDim.x) {
                    int ry = kk / nwx;
                    int y  = ys0 + ry;
                    int xw = xw0 + (kk - ry * nwx);
                    unsigned int cw = sm_mask[y * WPR + xw];
                    if (!cw) continue;
                    float sy = fminf(fmaxf(((float)y - (float)y0 + 0.5f) * scy - 0.5f, 0.0f), 27.0f);
                    int xlo2 = max(xs0, xw << 5);
                    int xhi2 = min(xs1, (xw << 5) + 32);
                    for (int x = xlo2; x < xhi2; x++) {
                        if (cw & (1u << (x & 31))) {
                            float sx = fminf(fmaxf(((float)x - (float)x0 + 0.5f) * scx - 0.5f, 0.0f), 27.0f);
                            if (bilin_ref(lg, sx, sy) > 0.0f) lo++;
                        }
                    }
                }
            }
            #pragma unroll
            for (int off = 16; off > 0; off >>= 1)
                lo += __shfl_down_sync(0xffffffffu, lo, off);
            if ((t & 31) == 0 && lo) atomicAdd(&s_ovl, lo);
        }
        __syncthreads();

        if (t == 0) {
            int kp = ((float)s_ovl <= 0.3f * (float)msum);
            s_keep = kp;
            g_keep[i] = kp;
        }
        __syncthreads();

        // merge only if kept AND a later ROI will still test against the mask
        if (s_keep && j < k - 1) {
            if (fits) {
                const unsigned int* bi = g_bits[i];
                for (int kk = t; kk < total; kk += blockDim.x) {
                    unsigned int b = bi[kk];
                    if (b) {
                        int ry = kk / nwx;
                        int xw = xw0 + (kk - ry * nwx);
                        sm_mask[(ys0 + ry) * WPR + xw] |= b;
                    }
                }
            } else {
                int o = sord[i];
                const float* lp = mask_prob + (long long)o * (MM * MM);
                for (int u = t; u < MM * MM; u += blockDim.x) lg[u] = lp[u];
                __syncthreads();
                float4 rb = reinterpret_cast<const float4*>(rois)[o];
                int x0 = (int)rb.x, y0 = (int)rb.y, x1 = (int)rb.z, y1 = (int)rb.w;
                float wv = fmaxf((float)(x1 - x0 + 1), 1.0f);
                float hv = fmaxf((float)(y1 - y0 + 1), 1.0f);
                float scx = 28.0f / wv, scy = 28.0f / hv;
                for (int kk = t; kk < total; kk += blockDim.x) {
                    int ry = kk / nwx;
                    int y  = ys0 + ry;
                    int xw = xw0 + (kk - ry * nwx);
                    float sy = fminf(fmaxf(((float)y - (float)y0 + 0.5f) * scy - 0.5f, 0.0f), 27.0f);
                    int xlo2 = max(xs0, xw << 5);
                    int xhi2 = min(xs1, (xw << 5) + 32);
                    unsigned int bits = 0u;
                    for (int x = xlo2; x < xhi2; x++) {
                        float sx = fminf(fmaxf(((float)x - (float)x0 + 0.5f) * scx - 0.5f, 0.0f), 27.0f);
                        if (bilin_ref(lg, sx, sy) > 0.0f) bits |= (1u << (x & 31));
                    }
                    if (bits) sm_mask[y * WPR + xw] |= bits;
                }
            }
            mask_ne = true;
        }
        __syncthreads();
    }
}

// ---------------------------------------------------------------------------
// grid (N+1, NSPLIT): CTAs [0,N) paste a y-slice; CTA N writes keep_inds.
__global__ __launch_bounds__(256) void k_paste(const float* __restrict__ rois,
                                               const float* __restrict__ prob,
                                               const float* __restrict__ mask_prob,
                                               float* __restrict__ out_keep,
                                               float* __restrict__ energy,
                                               int N, int has_keep) {
    __shared__ float sp[MAXN];
    __shared__ int   sord[MAXN];
    __shared__ int   kv[MAXN];
    __shared__ int   pf[MAXN];
    __shared__ float lg[MM * MM];
    __shared__ float2 s_cx[BOXMAX];

    int t = threadIdx.x;
    stage_sort(prob, N, sp, sord);

    if (t < MAXN) {
        int k = (t < N) ? g_keep[t] : 0;
        kv[t] = k;
        pf[t] = k;
    }
    __syncthreads();
    #pragma unroll
    for (int off = 1; off < MAXN; off <<= 1) {
        int v = (t < MAXN && t >= off) ? pf[t - off] : 0;
        __syncthreads();
        if (t < MAXN) pf[t] += v;
        __syncthreads();
    }

    int i = blockIdx.x;
    if (i >= N) {
        if (blockIdx.y != 0 || !has_keep) return;
        int nk = pf[N - 1];
        if (t < N) {
            if (kv[t]) out_keep[pf[t] - 1] = (float)sord[t];
            if (t >= nk) out_keep[t] = -1.0f;
        }
        return;
    }

    if (!kv[i]) return;
    int slot = pf[i] - 1;

    int o = sord[i];
    float4 rb = reinterpret_cast<const float4*>(rois)[o];
    int x0 = (int)rb.x, y0 = (int)rb.y, x1 = (int)rb.z, y1 = (int)rb.w;
    int xs0 = max(x0, 0), xs1 = min(x1 + 1, IMG_W);
    int ys0 = max(y0, 0), ys1 = min(y1 + 1, IMG_H);
    int bw = xs1 - xs0, bh = ys1 - ys0;
    if (bw <= 0 || bh <= 0) return;

    const float* lp = mask_prob + (long long)o * (MM * MM);
    for (int u = t; u < MM * MM; u += blockDim.x) lg[u] = lp[u];

    float wv = fmaxf((float)(x1 - x0 + 1), 1.0f);
    float hv = fmaxf((float)(y1 - y0 + 1), 1.0f);
    float scx = 28.0f / wv, scy = 28.0f / hv;

    bool pre = (bw <= BOXMAX);
    if (pre) {
        for (int u = t; u < bw; u += blockDim.x) {
            float sx = fminf(fmaxf(((float)(xs0 + u) - (float)x0 + 0.5f) * scx - 0.5f, 0.0f), 27.0f);
            int ix0 = (int)sx;
            s_cx[u] = make_float2(sx - (float)ix0, __int_as_float(ix0));
        }
    }
    __syncthreads();

    int chunk = (bh + NSPLIT - 1) / NSPLIT;
    int ry0   = blockIdx.y * chunk;
    int rows  = min(chunk, bh - ry0);
    if (rows <= 0) return;

    int xw0 = xs0 >> 5, xw1 = (xs1 + 31) >> 5;
    int warp = t >> 5;
    int lane = t & 31;
    int nwarps = blockDim.x >> 5;

    float* base = energy + (long long)slot * IMG_H * IMG_W;

    for (int r = warp; r < rows; r += nwarps) {
        int ry = ry0 + r;
        int y  = ys0 + ry;
        float sy = fminf(fmaxf(((float)y - (float)y0 + 0.5f) * scy - 0.5f, 0.0f), 27.0f);
        int iy0 = (int)sy;
        int iy1 = min(iy0 + 1, MM - 1);
        float fy = sy - (float)iy0;
        int ll = min(lane, MM - 1);
        float r0v = lg[iy0 * MM + ll];
        float r1v = lg[iy1 * MM + ll];
        float* rowp = base + y * IMG_W;

        for (int xw = xw0; xw < xw1; xw++) {
            int x = (xw << 5) + lane;
            bool inb = (x >= xs0) && (x < xs1);
            float val;
            if (pre) {
                float2 cf = s_cx[inb ? (x - xs0) : 0];
                float fx = cf.x;
                int ix0 = __float_as_int(cf.y);
                int ix1 = min(ix0 + 1, MM - 1);
                float v00 = __shfl_sync(0xffffffffu, r0v, ix0);
                float v01 = __shfl_sync(0xffffffffu, r0v, ix1);
                float v10 = __shfl_sync(0xffffffffu, r1v, ix0);
                float v11 = __shfl_sync(0xffffffffu, r1v, ix1);
                val = (1.0f - fy) * ((1.0f - fx) * v00 + fx * v01)
                    +         fy  * ((1.0f - fx) * v10 + fx * v11);
            } else {
                float sx = fminf(fmaxf(((float)x - (float)x0 + 0.5f) * scx - 0.5f, 0.0f), 27.0f);
                val = bilin_ref(lg, sx, sy);
            }
            if (inb) rowp[x] = val;
        }
    }
}

// ---------------------------------------------------------------------------
extern "C" void kernel_launch(void* const* d_in, const int* in_sizes, int n_in,
                              void* d_out, int out_size) {
    const float* rois  = (const float*)d_in[0];
    const float* prob  = (const float*)d_in[1];
    const float* mp    = (const float*)d_in[2];
    const int*   cidx  = (const int*)d_in[3];

    int N = in_sizes[1];
    if (N > MAXN) N = MAXN;

    float* out = (float*)d_out;
    long long HW = (long long)IMG_H * IMG_W;
    int has_keep = ((long long)out_size == (long long)N + (long long)N * HW) ? 1 : 0;
    float* energy = out + (has_keep ? N : 0);
    long long n4 = ((long long)N * HW) / 4;

    static bool attr_set = false;
    if (!attr_set) {
        cudaFuncSetAttribute(k_scan, cudaFuncAttributeMaxDynamicSharedMemorySize,
                             CMASK_BYTES);
        attr_set = true;
    }

    k_bits<<<dim3(N, ZSPLIT + NSPLIT), 256>>>(rois, prob, mp, (float4*)energy, n4, N);
    k_scan<<<NCLS, 256, CMASK_BYTES>>>(rois, prob, cidx, mp, N);
    k_paste<<<dim3(N + 1, NSPLIT), 256>>>(rois, prob, mp, out, energy, N, has_keep);
}

// round 11
// speedup vs baseline: 1.1170x; 1.1170x over previous
#include <cuda_runtime.h>

// ---------------------------------------------------------------------------
// MaskRemoval — R11: interleaved writer/raster dispatch + last-CTA compaction.
//   k_bits  : grid (N,24). y%3<2 -> zero-writer (2:1 interleave with rasters
//             in dispatch order). y%3==2 -> raster slice y/3.
//   k_scan  : grid (NCLS). per-class suppression; the LAST CTA to finish
//             (atomic ticket) compacts keep flags -> g_po/g_nk + keep_inds.
//   k_paste : grid (N,8). slot -> g_po[slot]; pure bilinear paste, no staging.
// ---------------------------------------------------------------------------

#define MAXN   128
#define NCLS   80
#define MM     28
#define IMG_H  800
#define IMG_W  800
#define WPR    25                      // 800/32 words per image row
#define BOXMAX 384
#define NSPLIT 8                       // raster y-slices per ROI
#define ZSPLIT 16                      // zero-writer CTA columns
#define YDIM   (ZSPLIT + NSPLIT)       // 24
#define BITSW  8192                    // words of bit-scratch per ROI
#define CMASK_BYTES (IMG_H * WPR * 4)  // 80000 B dynamic smem for k_scan

__device__ int g_keep[MAXN];
__device__ int g_msumP[MAXN][NSPLIT];            // per-slice popcounts
__device__ unsigned int g_bits[MAXN][BITSW];     // 4 MB ROI bit rasters
__device__ int g_done = 0;                       // scan arrival ticket
__device__ int g_po[MAXN];                       // slot -> original roi idx
__device__ int g_nk;                             // number of kept slots

// exact reference bilinear form (keep decision thresholds on val>0)
__device__ __forceinline__ float bilin_ref(const float* lg, float sx, float sy) {
    int ix0 = (int)sx;
    int iy0 = (int)sy;
    int ix1 = min(ix0 + 1, MM - 1);
    int iy1 = min(iy0 + 1, MM - 1);
    float fx = sx - (float)ix0;
    float fy = sy - (float)iy0;
    float v00 = lg[iy0 * MM + ix0], v01 = lg[iy0 * MM + ix1];
    float v10 = lg[iy1 * MM + ix0], v11 = lg[iy1 * MM + ix1];
    return (1.0f - fy) * ((1.0f - fx) * v00 + fx * v01)
         +         fy  * ((1.0f - fx) * v10 + fx * v11);
}

// stable descending rank sort into smem: sord[rank] = original index
__device__ __forceinline__ void stage_sort(const float* __restrict__ prob,
                                           int N, float* sp, int* sord) {
    int t = threadIdx.x;
    if (t < N) sp[t] = prob[t];
    __syncthreads();
    if (t < N) {
        float pi = sp[t];
        int r = 0;
        for (int j = 0; j < N; j++) {
            float pj = sp[j];
            r += (pj > pi) || (pj == pi && j < t);
        }
        sord[r] = t;
    }
    __syncthreads();
}

// ---------------------------------------------------------------------------
// grid (N, YDIM): role interleaved 2:1 in blockIdx.y (dispatch order).
__global__ __launch_bounds__(256) void k_bits(const float* __restrict__ rois,
                                              const float* __restrict__ prob,
                                              const float* __restrict__ mask_prob,
                                              float4* __restrict__ energy4,
                                              long long n4, int N) {
    int ymod = blockIdx.y % 3;
    if (ymod != 2) {
        // zero-writer; widx in [0, ZSPLIT)
        int widx = (blockIdx.y / 3) * 2 + ymod;
        long long wid = (long long)blockIdx.x + (long long)N * widx;
        long long nthreads = (long long)N * ZSPLIT * blockDim.x;
        long long i = wid * blockDim.x + threadIdx.x;
        float4 z = make_float4(0.f, 0.f, 0.f, 0.f);
        long long s4 = 4 * nthreads;
        for (; i + 3 * nthreads < n4; i += s4) {
            __stcs(&energy4[i], z);
            __stcs(&energy4[i + nthreads], z);
            __stcs(&energy4[i + 2 * nthreads], z);
            __stcs(&energy4[i + 3 * nthreads], z);
        }
        for (; i < n4; i += nthreads) __stcs(&energy4[i], z);
        return;
    }
    int slice = blockIdx.y / 3;        // 0..7

    __shared__ float sp[MAXN];
    __shared__ int   sord[MAXN];
    __shared__ float lg[MM * MM];
    __shared__ float2 s_cx[BOXMAX];
    __shared__ int   s_cnt;

    int i = blockIdx.x;
    if (i >= N) return;
    stage_sort(prob, N, sp, sord);

    int o = sord[i];
    float4 rb = reinterpret_cast<const float4*>(rois)[o];
    int x0 = (int)rb.x, y0 = (int)rb.y, x1 = (int)rb.z, y1 = (int)rb.w;
    int xs0 = max(x0, 0), xs1 = min(x1 + 1, IMG_W);
    int ys0 = max(y0, 0), ys1 = min(y1 + 1, IMG_H);
    int bw = xs1 - xs0, bh = ys1 - ys0;
    if (bw <= 0 || bh <= 0) return;        // g_msumP slot never written => 0

    if (threadIdx.x == 0) s_cnt = 0;
    const float* lp = mask_prob + (long long)o * (MM * MM);
    for (int t = threadIdx.x; t < MM * MM; t += blockDim.x) lg[t] = lp[t];

    float wv = fmaxf((float)(x1 - x0 + 1), 1.0f);
    float hv = fmaxf((float)(y1 - y0 + 1), 1.0f);
    float scx = 28.0f / wv, scy = 28.0f / hv;

    bool pre = (bw <= BOXMAX);
    if (pre) {
        for (int t = threadIdx.x; t < bw; t += blockDim.x) {
            float sx = fminf(fmaxf(((float)(xs0 + t) - (float)x0 + 0.5f) * scx - 0.5f, 0.0f), 27.0f);
            int ix0 = (int)sx;
            s_cx[t] = make_float2(sx - (float)ix0, __int_as_float(ix0));
        }
    }
    __syncthreads();

    int chunk = (bh + NSPLIT - 1) / NSPLIT;
    int ry0   = slice * chunk;
    int rows  = min(chunk, bh - ry0);
    if (rows <= 0) return;

    int xw0 = xs0 >> 5, xw1 = (xs1 + 31) >> 5;
    int nwx = xw1 - xw0;
    bool fits = (nwx * bh <= BITSW);

    int warp = threadIdx.x >> 5;
    int lane = threadIdx.x & 31;
    int nwarps = blockDim.x >> 5;
    int lm = 0;

    for (int r = warp; r < rows; r += nwarps) {
        int ry = ry0 + r;
        int y  = ys0 + ry;
        float sy = fminf(fmaxf(((float)y - (float)y0 + 0.5f) * scy - 0.5f, 0.0f), 27.0f);
        int iy0 = (int)sy;
        int iy1 = min(iy0 + 1, MM - 1);
        float fy = sy - (float)iy0;
        int ll = min(lane, MM - 1);
        float r0v = lg[iy0 * MM + ll];
        float r1v = lg[iy1 * MM + ll];

        unsigned int* dst = fits ? &g_bits[i][ry * nwx] : nullptr;
        for (int xw = xw0; xw < xw1; xw++) {
            int x = (xw << 5) + lane;
            bool inb = (x >= xs0) && (x < xs1);
            float val;
            if (pre) {
                float2 cf = s_cx[inb ? (x - xs0) : 0];
                float fx = cf.x;
                int ix0 = __float_as_int(cf.y);
                int ix1 = min(ix0 + 1, MM - 1);
                float v00 = __shfl_sync(0xffffffffu, r0v, ix0);
                float v01 = __shfl_sync(0xffffffffu, r0v, ix1);
                float v10 = __shfl_sync(0xffffffffu, r1v, ix0);
                float v11 = __shfl_sync(0xffffffffu, r1v, ix1);
                val = (1.0f - fy) * ((1.0f - fx) * v00 + fx * v01)
                    +         fy  * ((1.0f - fx) * v10 + fx * v11);
            } else {
                float sx = fminf(fmaxf(((float)x - (float)x0 + 0.5f) * scx - 0.5f, 0.0f), 27.0f);
                val = bilin_ref(lg, sx, sy);
            }
            bool on = inb && (val > 0.0f);
            unsigned int bits = __ballot_sync(0xffffffffu, on);
            if (lane == 0) {
                if (dst) dst[xw - xw0] = bits;
                lm += __popc(bits);
            }
        }
    }
    if (lane == 0 && lm) atomicAdd(&s_cnt, lm);
    __syncthreads();
    if (threadIdx.x == 0) g_msumP[i][slice] = s_cnt;
}

// ---------------------------------------------------------------------------
// Per-class suppression; last-arriving CTA compacts slots + writes keep_inds.
__global__ __launch_bounds__(256) void k_scan(const float* __restrict__ rois,
                                              const float* __restrict__ prob,
                                              const int*   __restrict__ clsidx,
                                              const float* __restrict__ mask_prob,
                                              float* __restrict__ out_keep,
                                              int N, int has_keep) {
    extern __shared__ unsigned int sm_mask[];               // IMG_H*WPR words
    __shared__ float sp[MAXN];
    __shared__ int   sord[MAXN];
    __shared__ int   scls[MAXN];
    __shared__ int   s_list[MAXN];
    __shared__ int   pf[MAXN];
    __shared__ int   s_k, s_ticket;
    __shared__ int   s_gx0[16], s_gx1[16], s_gy0[16], s_gy1[16];
    __shared__ int   s_ext[4];
    __shared__ int   s_ovl, s_keep;
    __shared__ float lg[MM * MM];

    int c = blockIdx.x;
    int t = threadIdx.x;

    // self-staging sort + class per sorted slot
    if (t < N) sp[t] = prob[t];
    __syncthreads();
    if (t < N) {
        float pi = sp[t];
        int r = 0;
        for (int j = 0; j < N; j++) {
            float pj = sp[j];
            r += (pj > pi) || (pj == pi && j < t);
        }
        sord[r] = t;
        scls[r] = clsidx[t] - 1;
    }
    __syncthreads();

    if (t == 0) {
        int k = 0;
        for (int i = 0; i < N; i++)
            if (scls[i] == c) s_list[k++] = i;
        s_k = k;
    }
    __syncthreads();
    int k = s_k;

    if (k == 1) {
        if (t == 0) {
            int i = s_list[0];
            int msum = 0;
            #pragma unroll
            for (int u = 0; u < NSPLIT; u++) msum += g_msumP[i][u];
            g_keep[i] = (msum > 0);
        }
    } else if (k >= 2) {
        int kc = min(k, 16);
        if (t < kc) {
            int i = s_list[t];
            float4 rb = reinterpret_cast<const float4*>(rois)[sord[i]];
            s_gx0[t] = max((int)rb.x, 0);
            s_gx1[t] = min((int)rb.z + 1, IMG_W);
            s_gy0[t] = max((int)rb.y, 0);
            s_gy1[t] = min((int)rb.w + 1, IMG_H);
        }
        __syncthreads();
        if (t == 0) {
            int ux0 = IMG_W, ux1 = 0, uy0 = IMG_H, uy1 = 0;
            for (int j = 0; j < kc; j++) {
                if (s_gx0[j] < s_gx1[j] && s_gy0[j] < s_gy1[j]) {
                    ux0 = min(ux0, s_gx0[j]); ux1 = max(ux1, s_gx1[j]);
                    uy0 = min(uy0, s_gy0[j]); uy1 = max(uy1, s_gy1[j]);
                }
            }
            s_ext[0] = ux0 >> 5;
            s_ext[1] = (ux1 + 31) >> 5;
            s_ext[2] = uy0;
            s_ext[3] = uy1;
        }
        __syncthreads();
        int uw0 = s_ext[0], uw1 = s_ext[1], uy0 = s_ext[2], uy1 = s_ext[3];
        int unw = max(uw1 - uw0, 0);
        int unrows = max(uy1 - uy0, 0);

        for (int w = t; w < unw * unrows; w += blockDim.x) {
            int r = w / unw;
            sm_mask[(uy0 + r) * WPR + uw0 + (w - r * unw)] = 0u;
        }
        __syncthreads();

        bool mask_ne = false;

        for (int j = 0; j < k; j++) {
            int i = s_list[j];
            int msum = 0;
            #pragma unroll
            for (int u = 0; u < NSPLIT; u++) msum += g_msumP[i][u];
            if (msum == 0) { if (t == 0) g_keep[i] = 0; continue; }

            int xs0, xs1, ys0, ys1;
            if (j < 16) {
                xs0 = s_gx0[j]; xs1 = s_gx1[j]; ys0 = s_gy0[j]; ys1 = s_gy1[j];
            } else {
                float4 rb = reinterpret_cast<const float4*>(rois)[sord[i]];
                xs0 = max((int)rb.x, 0); xs1 = min((int)rb.z + 1, IMG_W);
                ys0 = max((int)rb.y, 0); ys1 = min((int)rb.w + 1, IMG_H);
            }
            int bh = ys1 - ys0;
            int xw0 = xs0 >> 5, xw1 = (xs1 + 31) >> 5;
            int nwx = xw1 - xw0;
            int total = nwx * bh;
            bool fits = (total <= BITSW);

            if (t == 0) s_ovl = 0;
            __syncthreads();

            if (mask_ne) {
                int lo = 0;
                if (fits) {
                    const unsigned int* bi = g_bits[i];
                    for (int kk = t; kk < total; kk += blockDim.x) {
                        unsigned int b = bi[kk];
                        if (b) {
                            int ry = kk / nwx;
                            int xw = xw0 + (kk - ry * nwx);
                            lo += __popc(b & sm_mask[(ys0 + ry) * WPR + xw]);
                        }
                    }
                } else {
                    int o = sord[i];
                    const float* lp = mask_prob + (long long)o * (MM * MM);
                    for (int u = t; u < MM * MM; u += blockDim.x) lg[u] = lp[u];
                    __syncthreads();
                    float4 rb = reinterpret_cast<const float4*>(rois)[o];
                    int x0 = (int)rb.x, y0 = (int)rb.y, x1 = (int)rb.z, y1 = (int)rb.w;
                    float wv = fmaxf((float)(x1 - x0 + 1), 1.0f);
                    float hv = fmaxf((float)(y1 - y0 + 1), 1.0f);
                    float scx = 28.0f / wv, scy = 28.0f / hv;
                    for (int kk = t; kk < total; kk += blockDim.x) {
                        int ry = kk / nwx;
                        int y  = ys0 + ry;
                        int xw = xw0 + (kk - ry * nwx);
                        unsigned int cw = sm_mask[y * WPR + xw];
                        if (!cw) continue;
                        float sy = fminf(fmaxf(((float)y - (float)y0 + 0.5f) * scy - 0.5f, 0.0f), 27.0f);
                        int xlo2 = max(xs0, xw << 5);
                        int xhi2 = min(xs1, (xw << 5) + 32);
                        for (int x = xlo2; x < xhi2; x++) {
                            if (cw & (1u << (x & 31))) {
                                float sx = fminf(fmaxf(((float)x - (float)x0 + 0.5f) * scx - 0.5f, 0.0f), 27.0f);
                                if (bilin_ref(lg, sx, sy) > 0.0f) lo++;
                            }
                        }
                    }
                }
                #pragma unroll
                for (int off = 16; off > 0; off >>= 1)
                    lo += __shfl_down_sync(0xffffffffu, lo, off);
                if ((t & 31) == 0 && lo) atomicAdd(&s_ovl, lo);
            }
            __syncthreads();

            if (t == 0) {
                int kp = ((float)s_ovl <= 0.3f * (float)msum);
                s_keep = kp;
                g_keep[i] = kp;
            }
            __syncthreads();

            if (s_keep && j < k - 1) {
                if (fits) {
                    const unsigned int* bi = g_bits[i];
                    for (int kk = t; kk < total; kk += blockDim.x) {
                        unsigned int b = bi[kk];
                        if (b) {
                            int ry = kk / nwx;
                            int xw = xw0 + (kk - ry * nwx);
                            sm_mask[(ys0 + ry) * WPR + xw] |= b;
                        }
                    }
                } else {
                    int o = sord[i];
                    const float* lp = mask_prob + (long long)o * (MM * MM);
                    for (int u = t; u < MM * MM; u += blockDim.x) lg[u] = lp[u];
                    __syncthreads();
                    float4 rb = reinterpret_cast<const float4*>(rois)[o];
                    int x0 = (int)rb.x, y0 = (int)rb.y, x1 = (int)rb.z, y1 = (int)rb.w;
                    float wv = fmaxf((float)(x1 - x0 + 1), 1.0f);
                    float hv = fmaxf((float)(y1 - y0 + 1), 1.0f);
                    float scx = 28.0f / wv, scy = 28.0f / hv;
                    for (int kk = t; kk < total; kk += blockDim.x) {
                        int ry = kk / nwx;
                        int y  = ys0 + ry;
                        int xw = xw0 + (kk - ry * nwx);
                        float sy = fminf(fmaxf(((float)y - (float)y0 + 0.5f) * scy - 0.5f, 0.0f), 27.0f);
                        int xlo2 = max(xs0, xw << 5);
                        int xhi2 = min(xs1, (xw << 5) + 32);
                        unsigned int bits = 0u;
                        for (int x = xlo2; x < xhi2; x++) {
                            float sx = fminf(fmaxf(((float)x - (float)x0 + 0.5f) * scx - 0.5f, 0.0f), 27.0f);
                            if (bilin_ref(lg, sx, sy) > 0.0f) bits |= (1u << (x & 31));
                        }
                        if (bits) sm_mask[y * WPR + xw] |= bits;
                    }
                }
                mask_ne = true;
            }
            __syncthreads();
        }
    }

    // ---- arrival ticket; last CTA compacts ---------------------------------
    __syncthreads();
    if (t == 0) {
        __threadfence();                       // publish g_keep
        s_ticket = atomicAdd(&g_done, 1);
    }
    __syncthreads();
    if (s_ticket != gridDim.x - 1) return;

    __threadfence();                           // acquire all g_keep
    int kv = (t < N) ? g_keep[t] : 0;
    if (t < MAXN) pf[t] = kv;
    __syncthreads();
    #pragma unroll
    for (int off = 1; off < MAXN; off <<= 1) {
        int v = (t < MAXN && t >= off) ? pf[t - off] : 0;
        __syncthreads();
        if (t < MAXN) pf[t] += v;
        __syncthreads();
    }
    int nk = pf[N - 1];
    if (t < N) {
        if (kv) {
            g_po[pf[t] - 1] = sord[t];
            if (has_keep) out_keep[pf[t] - 1] = (float)sord[t];
        }
        if (has_keep && t >= nk) out_keep[t] = -1.0f;
    }
    if (t == 0) {
        g_nk = nk;
        g_done = 0;                            // reset for next launch
        __threadfence();
    }
}

// ---------------------------------------------------------------------------
// grid (N, NSPLIT): pure paste, slot table precomputed by k_scan.
__global__ __launch_bounds__(256) void k_paste(const float* __restrict__ rois,
                                               const float* __restrict__ mask_prob,
                                               float* __restrict__ energy) {
    int slot = blockIdx.x;
    if (slot >= g_nk) return;
    int o = g_po[slot];

    __shared__ float lg[MM * MM];
    __shared__ float2 s_cx[BOXMAX];

    int t = threadIdx.x;
    float4 rb = reinterpret_cast<const float4*>(rois)[o];
    int x0 = (int)rb.x, y0 = (int)rb.y, x1 = (int)rb.z, y1 = (int)rb.w;
    int xs0 = max(x0, 0), xs1 = min(x1 + 1, IMG_W);
    int ys0 = max(y0, 0), ys1 = min(y1 + 1, IMG_H);
    int bw = xs1 - xs0, bh = ys1 - ys0;
    if (bw <= 0 || bh <= 0) return;

    const float* lp = mask_prob + (long long)o * (MM * MM);
    for (int u = t; u < MM * MM; u += blockDim.x) lg[u] = lp[u];

    float wv = fmaxf((float)(x1 - x0 + 1), 1.0f);
    float hv = fmaxf((float)(y1 - y0 + 1), 1.0f);
    float scx = 28.0f / wv, scy = 28.0f / hv;

    bool pre = (bw <= BOXMAX);
    if (pre) {
        for (int u = t; u < bw; u += blockDim.x) {
            float sx = fminf(fmaxf(((float)(xs0 + u) - (float)x0 + 0.5f) * scx - 0.5f, 0.0f), 27.0f);
            int ix0 = (int)sx;
            s_cx[u] = make_float2(sx - (float)ix0, __int_as_float(ix0));
        }
    }
    __syncthreads();

    int chunk = (bh + NSPLIT - 1) / NSPLIT;
    int ry0   = blockIdx.y * chunk;
    int rows  = min(chunk, bh - ry0);
    if (rows <= 0) return;

    int xw0 = xs0 >> 5, xw1 = (xs1 + 31) >> 5;
    int warp = t >> 5;
    int lane = t & 31;
    int nwarps = blockDim.x >> 5;

    float* base = energy + (long long)slot * IMG_H * IMG_W;

    for (int r = warp; r < rows; r += nwarps) {
        int ry = ry0 + r;
        int y  = ys0 + ry;
        float sy = fminf(fmaxf(((float)y - (float)y0 + 0.5f) * scy - 0.5f, 0.0f), 27.0f);
        int iy0 = (int)sy;
        int iy1 = min(iy0 + 1, MM - 1);
        float fy = sy - (float)iy0;
        int ll = min(lane, MM - 1);
        float r0v = lg[iy0 * MM + ll];
        float r1v = lg[iy1 * MM + ll];
        float* rowp = base + y * IMG_W;

        for (int xw = xw0; xw < xw1; xw++) {
            int x = (xw << 5) + lane;
            bool inb = (x >= xs0) && (x < xs1);
            float val;
            if (pre) {
                float2 cf = s_cx[inb ? (x - xs0) : 0];
                float fx = cf.x;
                int ix0 = __float_as_int(cf.y);
                int ix1 = min(ix0 + 1, MM - 1);
                float v00 = __shfl_sync(0xffffffffu, r0v, ix0);
                float v01 = __shfl_sync(0xffffffffu, r0v, ix1);
                float v10 = __shfl_sync(0xffffffffu, r1v, ix0);
                float v11 = __shfl_sync(0xffffffffu, r1v, ix1);
                val = (1.0f - fy) * ((1.0f - fx) * v00 + fx * v01)
                    +         fy  * ((1.0f - fx) * v10 + fx * v11);
            } else {
                float sx = fminf(fmaxf(((float)x - (float)x0 + 0.5f) * scx - 0.5f, 0.0f), 27.0f);
                val = bilin_ref(lg, sx, sy);
            }
            if (inb) rowp[x] = val;
        }
    }
}

// ---------------------------------------------------------------------------
extern "C" void kernel_launch(void* const* d_in, const int* in_sizes, int n_in,
                              void* d_out, int out_size) {
    const float* rois  = (const float*)d_in[0];
    const float* prob  = (const float*)d_in[1];
    const float* mp    = (const float*)d_in[2];
    const int*   cidx  = (const int*)d_in[3];

    int N = in_sizes[1];
    if (N > MAXN) N = MAXN;

    float* out = (float*)d_out;
    long long HW = (long long)IMG_H * IMG_W;
    int has_keep = ((long long)out_size == (long long)N + (long long)N * HW) ? 1 : 0;
    float* energy = out + (has_keep ? N : 0);
    long long n4 = ((long long)N * HW) / 4;

    static bool attr_set = false;
    if (!attr_set) {
        cudaFuncSetAttribute(k_scan, cudaFuncAttributeMaxDynamicSharedMemorySize,
                             CMASK_BYTES);
        attr_set = true;
    }

    k_bits<<<dim3(N, YDIM), 256>>>(rois, prob, mp, (float4*)energy, n4, N);
    k_scan<<<NCLS, 256, CMASK_BYTES>>>(rois, prob, cidx, mp, out, N, has_keep);
    k_paste<<<dim3(N, NSPLIT), 256>>>(rois, mp, energy);
}